// round 12
// baseline (speedup 1.0000x reference)
#include <cuda_runtime.h>
#include <cuda_bf16.h>
#include <cstdint>

// ---------------------------------------------------------------------------
// Model_70222715289880: bilinear score -> top-k(10/64) -> gather of 10 tensors
// B=8, K=64, TOPK=10, N_R=4, L_R=128, H=512, D=128, D2=640.
//
// R12: separate q/score (R10 structure; R11 fusion measured neutral/harmful)
// with q's 2-group cp.async split; gather wave-quantization fix: 1184 h_r
// blocks (one full wave @ occ 8) grid-striding 2560 chunks, small segments
// scheduled first (bids 0..127).
// FP summation order is BIT-IDENTICAL to all passing rounds (R2-R11).
// ---------------------------------------------------------------------------

#define Bq   8
#define Kk   64
#define TOPK 10
#define D2   640

#define OFF_SCORES   0
#define OFF_RATINGS  21238160
#define OFF_IDX      21248480

// vec4 (float4) offsets of gathered segments in dst
#define V4_SR    20u
#define V4_HR    40980u
#define V4_RA    5283860u
#define V4_RO    5294100u
#define V4_MASK  5304340u
#define V4_RB    5304420u
#define V4_RM    5306980u
#define V4_RE    5309560u

// small-gather compacted ranges (f4 units), h_r excluded
#define SM_SR_END  40960u
#define SM_RA_END  51200u
#define SM_RO_END  61440u
#define SM_MK_END  61520u
#define SM_RB_END  64080u
#define SM_RM_END  66640u
#define SM_TOTAL   69200u

#define SM_BLOCKS  128
#define HR_UNITS   2560u   // 80 rows * 32 chunks (2048 f4 each)
#define HR_BLOCKS  1184    // one full wave at 8 blocks/SM on 148 SMs

__device__ int   g_topk_idx[Bq * TOPK];
__device__ float g_q[Bq * D2];

// -------------------------------- cp.async --------------------------------
__device__ __forceinline__ void cpa16(uint32_t dst_smem, const void* src) {
    asm volatile("cp.async.cg.shared.global [%0], [%1], 16;"
                 :: "r"(dst_smem), "l"(src));
}
#define CPA_COMMIT()  asm volatile("cp.async.commit_group;")
#define CPA_WAIT(N)   asm volatile("cp.async.wait_group %0;" :: "n"(N) : "memory")

__device__ __forceinline__ uint32_t smem_u32(const void* p) {
    return (uint32_t)__cvta_generic_to_shared(p);
}

// ---------------------------------------------------------------------------
// XLA's tanh (Eigen generic_fast_tanh_float as emitted by elemental_ir_emitter)
// ---------------------------------------------------------------------------
__device__ __forceinline__ float xla_tanhf(float x)
{
    const float kClamp = 7.90531110763549805f;
    float xc = fmaxf(-kClamp, fminf(x, kClamp));
    float x2 = xc * xc;

    float p = fmaf(x2, -2.76076847742355e-16f, 2.00018790482477e-13f);
    p = fmaf(x2, p, -8.60467152213735e-11f);
    p = fmaf(x2, p,  5.12229709037114e-08f);
    p = fmaf(x2, p,  1.48572235717979e-05f);
    p = fmaf(x2, p,  6.37261928875436e-04f);
    p = fmaf(x2, p,  4.89352455891786e-03f);
    p = xc * p;

    float q = fmaf(x2, 1.19825839466702e-06f, 1.18534705686654e-04f);
    q = fmaf(x2, q, 2.26843463243900e-03f);
    q = fmaf(x2, q, 4.89352518554385e-03f);

    float r = p / q;
    return (fabsf(x) < 0.0004f) ? x : r;
}

// total-order key on float (ascending)
__device__ __forceinline__ unsigned ord_f32(float f)
{
    int i = __float_as_int(f);
    return (i < 0) ? ~(unsigned)i : ((unsigned)i | 0x80000000u);
}

// ---------------------------------------------------------------------------
// Kernel Q: q[b][e] = sum_d a_s_q[b][d] * W[d][e]  (serial-d chain, d asc).
// 40 blocks x 128 threads (4 warps). Block (es=bid%20, bg=bid/20):
// e-slice [32es,+32), batches [4bg,+4). Warp w -> b = 4bg+w, lane l -> e.
// 2-group cp.async: group A = a_s_q + W rows 0..319; group B = rows 320..639.
// Chain over d<320 runs while group B lands. Dynamic smem: 102,400 B.
// ---------------------------------------------------------------------------
#define Q_SMEM  ((8 * D2 + D2 * 32) * 4)

__global__ __launch_bounds__(128) void q_kernel(
    const float* __restrict__ a_s_q,
    const float* __restrict__ W)
{
    extern __shared__ float dynq[];
    float* aq = dynq;                 // [8][640]
    float* wt = dynq + 8 * D2;        // [640][32]  row stride 32 floats

    const int tid = threadIdx.x;
    const int w   = tid >> 5;
    const int l   = tid & 31;
    const int es  = blockIdx.x % 20;
    const int bg  = blockIdx.x / 20;
    const int e0  = es * 32;

    const uint32_t aq_s = smem_u32(aq);
    const uint32_t wt_s = smem_u32(wt);

    // group A: a_s_q (1280 f4, 10/thread) + W rows 0..319 (2560 f4, 20/thread)
    #pragma unroll
    for (int r = 0; r < 10; ++r) {
        const int j = tid + 128 * r;
        cpa16(aq_s + (uint32_t)j * 16u, a_s_q + j * 4);
    }
    #pragma unroll
    for (int r = 0; r < 20; ++r) {
        const int j   = tid + 128 * r;          // 0..2559
        const int row = j >> 3;                 // 0..319
        const int c   = j & 7;
        cpa16(wt_s + (uint32_t)j * 16u, W + row * D2 + e0 + c * 4);
    }
    CPA_COMMIT();
    // group B: W rows 320..639
    #pragma unroll
    for (int r = 20; r < 40; ++r) {
        const int j   = tid + 128 * r;          // 2560..5119
        const int row = j >> 3;                 // 320..639
        const int c   = j & 7;
        cpa16(wt_s + (uint32_t)j * 16u, W + row * D2 + e0 + c * 4);
    }
    CPA_COMMIT();

    CPA_WAIT(1);
    __syncthreads();

    const int b = bg * 4 + w;
    const float* aqb = aq + b * D2;
    const float* wl  = wt + l;
    float s = 0.f;
    #pragma unroll 16
    for (int d = 0; d < 320; ++d)
        s = fmaf(aqb[d], wl[d * 32], s);

    CPA_WAIT(0);
    __syncthreads();
    #pragma unroll 16
    for (int d = 320; d < D2; ++d)
        s = fmaf(aqb[d], wl[d * 32], s);
    g_q[b * D2 + e0 + l] = s;
}

// ---------------------------------------------------------------------------
// Kernel S: scores + top-10 + small outputs. 8 blocks x 256 threads.
// ONE cp.async burst loads the whole a_s_r[b] block (64 x 640, rows padded
// to 652 -> conflict-free LDS) + q row. R2-identical dot (4 thr/k, stride-4
// chains, shfl 1,2) + warp top-k. Dynamic smem: 169,472 B.
// ---------------------------------------------------------------------------
#define SROW2   652
#define S_SMEM  ((D2 + Kk * SROW2) * 4)

__global__ __launch_bounds__(256) void score_topk_kernel(
    const float* __restrict__ a_s_r,
    const int*   __restrict__ ratings,
    float* __restrict__ out)
{
    __shared__ float sc[Kk];
    extern __shared__ float dyns[];
    float* q_s = dyns;             // [640]
    float* at  = dyns + D2;        // [64][652]

    const int b   = blockIdx.x;
    const int tid = threadIdx.x;

    // q row: 160 f4
    const uint32_t q_ss = smem_u32(q_s);
    if (tid < 160) cpa16(q_ss + (uint32_t)tid * 16u, g_q + b * D2 + tid * 4);

    // a_s_r block: 64 rows x 160 f4 = 10240 f4 -> 40 per thread
    const float* abase = a_s_r + (size_t)b * Kk * D2;
    const uint32_t at_s = smem_u32(at);
    #pragma unroll
    for (int r = 0; r < 40; ++r) {
        const int j   = tid + 256 * r;
        const int row = j / 160;
        const int col = j % 160;
        cpa16(at_s + (uint32_t)(row * SROW2 * 4 + col * 16),
              abase + row * D2 + col * 4);
    }
    CPA_COMMIT();
    CPA_WAIT(0);
    __syncthreads();

    const int k   = tid >> 2;
    const int sub = tid & 3;
    {
        const float* arow = at + k * SROW2 + sub;
        const float* qrow = q_s + sub;
        float s = 0.f;
        #pragma unroll 16
        for (int i = 0; i < 160; ++i)
            s = fmaf(qrow[4 * i], arow[4 * i], s);
        s += __shfl_xor_sync(0xFFFFFFFFu, s, 1);
        s += __shfl_xor_sync(0xFFFFFFFFu, s, 2);
        if (sub == 0) sc[k] = xla_tanhf(s);
    }
    __syncthreads();

    if (tid < 32) {
        const int lane = tid;
        // key = ord(score) << 7 | (127 - k): max key == max score, min index
        unsigned long long k0 =
            ((unsigned long long)ord_f32(sc[lane]) << 7) | (unsigned)(127 - lane);
        unsigned long long k1 =
            ((unsigned long long)ord_f32(sc[lane + 32]) << 7) | (unsigned)(127 - (lane + 32));

        #pragma unroll
        for (int t = 0; t < TOPK; ++t) {
            unsigned long long m = (k0 > k1) ? k0 : k1;
            #pragma unroll
            for (int o = 16; o > 0; o >>= 1) {
                unsigned long long other = __shfl_xor_sync(0xFFFFFFFFu, m, o);
                if (other > m) m = other;
            }
            const int bk = 127 - (int)(m & 127u);
            if (lane == 0) {
                out[OFF_SCORES  + b * TOPK + t] = sc[bk];
                out[OFF_RATINGS + b * TOPK + t] = (float)ratings[b * Kk + bk];
                out[OFF_IDX     + b * TOPK + t] = (float)bk;
                g_topk_idx[b * TOPK + t] = bk;
            }
            if (bk == lane)      k0 = 0ull;
            if (bk == lane + 32) k1 = 0ull;
        }
    }
}

// ---------------------------------------------------------------------------
// Kernel G: gather. Blocks [0, 128): small segments (scheduled FIRST so they
// don't extend the tail). Blocks [128, 1312): one full wave at occ 8;
// grid-stride over 2560 h_r chunk-units (row = u>>5, chunk = u&31), 32KB
// per unit, 8 independent f4 ld/st per thread with streaming hints.
// ---------------------------------------------------------------------------
__global__ __launch_bounds__(256) void gather_kernel(
    const float4* __restrict__ s_r,
    const float4* __restrict__ h_r,
    const float4* __restrict__ r_a,
    const float4* __restrict__ r_o,
    const float4* __restrict__ mask,
    const int4*   __restrict__ rb,
    const float4* __restrict__ rm,
    const int4*   __restrict__ re,
    float4* __restrict__ out4)
{
    __shared__ int idx_s[Bq * TOPK];
    if (threadIdx.x < Bq * TOPK) idx_s[threadIdx.x] = g_topk_idx[threadIdx.x];
    __syncthreads();

    if (blockIdx.x >= SM_BLOCKS) {
        for (unsigned u = blockIdx.x - SM_BLOCKS; u < HR_UNITS; u += HR_BLOCKS) {
            const unsigned row   = u >> 5;           // 0..79
            const unsigned chunk = u & 31u;          // 2048 f4 each
            const unsigned b     = row / TOPK;
            const unsigned k     = (unsigned)idx_s[row];
            const float4* src = h_r + (b * Kk + k) * 65536u + chunk * 2048u + threadIdx.x;
            float4*       dst = out4 + V4_HR + row * 65536u + chunk * 2048u + threadIdx.x;
            float4 v[8];
            #pragma unroll
            for (int i = 0; i < 8; ++i) v[i] = __ldcs(src + 256 * i);
            #pragma unroll
            for (int i = 0; i < 8; ++i) __stcs(dst + 256 * i, v[i]);
        }
        return;
    }

    const unsigned stride = SM_BLOCKS * 256u;
    for (unsigned g = blockIdx.x * 256u + threadIdx.x; g < SM_TOTAL; g += stride) {
        if (g < SM_SR_END) {
            const unsigned row = g >> 9;
            const unsigned iv  = g & 511u;
            const unsigned b   = row / TOPK;
            const unsigned k   = (unsigned)idx_s[row];
            out4[V4_SR + g] = s_r[(b * Kk + k) * 512u + iv];
        } else if (g < SM_RA_END) {
            const unsigned local = g - SM_SR_END;
            const unsigned row = local >> 7;
            const unsigned iv  = local & 127u;
            const unsigned b   = row / TOPK;
            const unsigned k   = (unsigned)idx_s[row];
            out4[V4_RA + local] = r_a[(b * Kk + k) * 128u + iv];
        } else if (g < SM_RO_END) {
            const unsigned local = g - SM_RA_END;
            const unsigned row = local >> 7;
            const unsigned iv  = local & 127u;
            const unsigned b   = row / TOPK;
            const unsigned k   = (unsigned)idx_s[row];
            out4[V4_RO + local] = r_o[(b * Kk + k) * 128u + iv];
        } else if (g < SM_MK_END) {
            const unsigned local = g - SM_RO_END;   // == row
            const unsigned b = local / TOPK;
            const unsigned k = (unsigned)idx_s[local];
            out4[V4_MASK + local] = mask[b * Kk + k];
        } else if (g < SM_RB_END) {
            const unsigned local = g - SM_MK_END;
            const unsigned row = local >> 5;
            const unsigned iv  = local & 31u;
            const unsigned b   = row / TOPK;
            const unsigned k   = (unsigned)idx_s[row];
            const int4 v = rb[(b * Kk + k) * 32u + iv];
            out4[V4_RB + local] = make_float4((float)v.x, (float)v.y, (float)v.z, (float)v.w);
        } else if (g < SM_RM_END) {
            const unsigned local = g - SM_RB_END;
            const unsigned row = local >> 5;
            const unsigned iv  = local & 31u;
            const unsigned b   = row / TOPK;
            const unsigned k   = (unsigned)idx_s[row];
            out4[V4_RM + local] = rm[(b * Kk + k) * 32u + iv];
        } else {
            const unsigned local = g - SM_RM_END;
            const unsigned row = local >> 5;
            const unsigned iv  = local & 31u;
            const unsigned b   = row / TOPK;
            const unsigned k   = (unsigned)idx_s[row];
            const int4 v = re[(b * Kk + k) * 32u + iv];
            out4[V4_RE + local] = make_float4((float)v.x, (float)v.y, (float)v.z, (float)v.w);
        }
    }
}

// ---------------------------------------------------------------------------
extern "C" void kernel_launch(void* const* d_in, const int* in_sizes, int n_in,
                              void* d_out, int out_size)
{
    const float* a_s_q   = (const float*)d_in[0];
    const float* a_s_r   = (const float*)d_in[1];
    const float* W       = (const float*)d_in[2];
    const float* s_r     = (const float*)d_in[3];
    const float* h_r     = (const float*)d_in[4];
    const float* r_a     = (const float*)d_in[5];
    const float* r_o     = (const float*)d_in[6];
    const float* mask    = (const float*)d_in[7];
    const int*   rb      = (const int*)d_in[8];
    const float* rm      = (const float*)d_in[9];
    const int*   ratings = (const int*)d_in[10];
    const int*   re      = (const int*)d_in[11];
    float* out = (float*)d_out;

    // opt-in to >48KB dynamic smem (host-side attribute; idempotent)
    static int attr_done = 0;
    if (!attr_done) {
        cudaFuncSetAttribute(q_kernel,
            cudaFuncAttributeMaxDynamicSharedMemorySize, Q_SMEM);
        cudaFuncSetAttribute(score_topk_kernel,
            cudaFuncAttributeMaxDynamicSharedMemorySize, S_SMEM);
        attr_done = 1;
    }

    q_kernel<<<40, 128, Q_SMEM>>>(a_s_q, W);
    score_topk_kernel<<<Bq, 256, S_SMEM>>>(a_s_r, ratings, out);
    gather_kernel<<<SM_BLOCKS + HR_BLOCKS, 256>>>(
        (const float4*)s_r, (const float4*)h_r, (const float4*)r_a,
        (const float4*)r_o, (const float4*)mask, (const int4*)rb,
        (const float4*)rm, (const int4*)re, (float4*)out);
}

// round 13
// speedup vs baseline: 1.0016x; 1.0016x over previous
#include <cuda_runtime.h>
#include <cuda_bf16.h>
#include <cstdint>

// ---------------------------------------------------------------------------
// Model_70222715289880: bilinear score -> top-k(10/64) -> gather of 10 tensors
// B=8, K=64, TOPK=10, N_R=4, L_R=128, H=512, D=128, D2=640.
//
// R13: halve per-SM serial work in the front kernels.
//  q: 80 blocks (2 batches each) -> per-SM LDS stream halved.
//  score: 16 half-k blocks (83KB bursts) -> drain+LDS halved; second
//  finisher per b runs the (unchanged) warp top-k from a global sc array.
// Gather unchanged. FP summation order BIT-IDENTICAL to R2-R12.
// ---------------------------------------------------------------------------

#define Bq   8
#define Kk   64
#define TOPK 10
#define D2   640

#define OFF_SCORES   0
#define OFF_RATINGS  21238160
#define OFF_IDX      21248480

// vec4 (float4) offsets of gathered segments in dst
#define V4_SR    20u
#define V4_HR    40980u
#define V4_RA    5283860u
#define V4_RO    5294100u
#define V4_MASK  5304340u
#define V4_RB    5304420u
#define V4_RM    5306980u
#define V4_RE    5309560u

// small-gather compacted ranges (f4 units), h_r excluded
#define SM_SR_END  40960u
#define SM_RA_END  51200u
#define SM_RO_END  61440u
#define SM_MK_END  61520u
#define SM_RB_END  64080u
#define SM_RM_END  66640u
#define SM_TOTAL   69200u

#define SM_BLOCKS  128
#define HR_UNITS   2560u   // 80 rows * 32 chunks (2048 f4 each)
#define HR_BLOCKS  1184    // one full wave at 8 blocks/SM on 148 SMs

__device__ int      g_topk_idx[Bq * TOPK];
__device__ float    g_q[Bq * D2];
__device__ float    g_sc[Bq * Kk];
__device__ unsigned g_scnt[Bq];   // zero-init; finisher resets each call

// -------------------------------- cp.async --------------------------------
__device__ __forceinline__ void cpa16(uint32_t dst_smem, const void* src) {
    asm volatile("cp.async.cg.shared.global [%0], [%1], 16;"
                 :: "r"(dst_smem), "l"(src));
}
#define CPA_COMMIT()  asm volatile("cp.async.commit_group;")
#define CPA_WAIT(N)   asm volatile("cp.async.wait_group %0;" :: "n"(N) : "memory")

__device__ __forceinline__ uint32_t smem_u32(const void* p) {
    return (uint32_t)__cvta_generic_to_shared(p);
}

// ---------------------------------------------------------------------------
// XLA's tanh (Eigen generic_fast_tanh_float as emitted by elemental_ir_emitter)
// ---------------------------------------------------------------------------
__device__ __forceinline__ float xla_tanhf(float x)
{
    const float kClamp = 7.90531110763549805f;
    float xc = fmaxf(-kClamp, fminf(x, kClamp));
    float x2 = xc * xc;

    float p = fmaf(x2, -2.76076847742355e-16f, 2.00018790482477e-13f);
    p = fmaf(x2, p, -8.60467152213735e-11f);
    p = fmaf(x2, p,  5.12229709037114e-08f);
    p = fmaf(x2, p,  1.48572235717979e-05f);
    p = fmaf(x2, p,  6.37261928875436e-04f);
    p = fmaf(x2, p,  4.89352455891786e-03f);
    p = xc * p;

    float q = fmaf(x2, 1.19825839466702e-06f, 1.18534705686654e-04f);
    q = fmaf(x2, q, 2.26843463243900e-03f);
    q = fmaf(x2, q, 4.89352518554385e-03f);

    float r = p / q;
    return (fabsf(x) < 0.0004f) ? x : r;
}

// total-order key on float (ascending)
__device__ __forceinline__ unsigned ord_f32(float f)
{
    int i = __float_as_int(f);
    return (i < 0) ? ~(unsigned)i : ((unsigned)i | 0x80000000u);
}

// ---------------------------------------------------------------------------
// Kernel Q: q[b][e] = sum_d a_s_q[b][d] * W[d][e]  (serial-d chain, d asc).
// 80 blocks x 128 threads. Block (es=bid%20, bg=bid/20): e-slice [32es,+32),
// batches {2bg, 2bg+1}. All 4 warps load; warps 0,1 run chains
// (b = 2bg + w, lane l -> e = 32es + l). Dynamic smem: 87,040 B.
// ---------------------------------------------------------------------------
#define Q_SMEM  ((2 * D2 + D2 * 32) * 4)

__global__ __launch_bounds__(128) void q_kernel(
    const float* __restrict__ a_s_q,
    const float* __restrict__ W)
{
    extern __shared__ float dynq[];
    float* aq = dynq;                 // [2][640]
    float* wt = dynq + 2 * D2;        // [640][32] row stride 32 floats

    const int tid = threadIdx.x;
    const int w   = tid >> 5;
    const int l   = tid & 31;
    const int es  = blockIdx.x % 20;
    const int bg  = blockIdx.x / 20;
    const int e0  = es * 32;

    const uint32_t aq_s = smem_u32(aq);
    const uint32_t wt_s = smem_u32(wt);

    // a_s_q rows 2bg, 2bg+1: 320 f4 (threads 0..127, 3 rounds w/ guard)
    const float* aqsrc = a_s_q + bg * 2 * D2;
    #pragma unroll
    for (int r = 0; r < 3; ++r) {
        const int j = tid + 128 * r;
        if (j < 320) cpa16(aq_s + (uint32_t)j * 16u, aqsrc + j * 4);
    }
    // W slice: 640 rows x 8 f4 = 5120 f4 -> 40 per thread
    #pragma unroll
    for (int r = 0; r < 40; ++r) {
        const int j   = tid + 128 * r;
        const int row = j >> 3;
        const int c   = j & 7;
        cpa16(wt_s + (uint32_t)j * 16u, W + row * D2 + e0 + c * 4);
    }
    CPA_COMMIT();
    CPA_WAIT(0);
    __syncthreads();

    if (w < 2) {
        const int b = bg * 2 + w;
        const float* aqb = aq + w * D2;
        const float* wl  = wt + l;
        float s = 0.f;
        #pragma unroll 16
        for (int d = 0; d < D2; ++d)
            s = fmaf(aqb[d], wl[d * 32], s);
        g_q[b * D2 + e0 + l] = s;
    }
}

// ---------------------------------------------------------------------------
// Kernel S: 16 blocks x 256 threads. Block (b=bid>>1, kh=bid&1) computes
// tanh scores for k in [32kh, 32kh+32) -> g_sc. Chain FP order identical
// to R2-R12 (4 thr/k, stride-4, shfl 1,2). Second finisher per b runs the
// warp top-k from g_sc and writes the small outputs + g_topk_idx.
// Dynamic smem: 86,016 B.
// ---------------------------------------------------------------------------
#define SROW2   652
#define S_SMEM  ((D2 + 32 * SROW2) * 4)

__global__ __launch_bounds__(256) void score_topk_kernel(
    const float* __restrict__ a_s_r,
    const int*   __restrict__ ratings,
    float* __restrict__ out)
{
    __shared__ int am_last;
    extern __shared__ float dyns[];
    float* q_s = dyns;             // [640]
    float* at  = dyns + D2;        // [32][652]

    const int b   = blockIdx.x >> 1;
    const int kh  = blockIdx.x & 1;
    const int tid = threadIdx.x;

    // q row: 160 f4
    const uint32_t q_ss = smem_u32(q_s);
    if (tid < 160) cpa16(q_ss + (uint32_t)tid * 16u, g_q + b * D2 + tid * 4);

    // a_s_r rows [32kh, +32): 32 x 160 f4 = 5120 f4 -> 20 per thread
    const float* abase = a_s_r + ((size_t)b * Kk + kh * 32) * D2;
    const uint32_t at_s = smem_u32(at);
    #pragma unroll
    for (int r = 0; r < 20; ++r) {
        const int j   = tid + 256 * r;
        const int row = j / 160;
        const int col = j % 160;
        cpa16(at_s + (uint32_t)(row * SROW2 * 4 + col * 16),
              abase + row * D2 + col * 4);
    }
    CPA_COMMIT();
    CPA_WAIT(0);
    __syncthreads();

    if (tid < 128) {
        const int kloc = tid >> 2;       // 0..31
        const int sub  = tid & 3;
        const float* arow = at + kloc * SROW2 + sub;
        const float* qrow = q_s + sub;
        float s = 0.f;
        #pragma unroll 16
        for (int i = 0; i < 160; ++i)
            s = fmaf(qrow[4 * i], arow[4 * i], s);
        s += __shfl_xor_sync(0xFFFFFFFFu, s, 1);
        s += __shfl_xor_sync(0xFFFFFFFFu, s, 2);
        if (sub == 0) g_sc[b * Kk + kh * 32 + kloc] = xla_tanhf(s);
    }
    __syncthreads();

    if (tid == 0) {
        __threadfence();
        unsigned r = atomicAdd(&g_scnt[b], 1u);
        am_last = (r == 1u) ? 1 : 0;
    }
    __syncthreads();
    if (!am_last) return;
    __threadfence();   // order g_sc reads after observing the other half

    if (tid < 32) {
        const int lane = tid;
        const float* scb = g_sc + b * Kk;
        const float s0 = scb[lane];
        const float s1 = scb[lane + 32];
        // key = ord(score) << 7 | (127 - k): max key == max score, min index
        unsigned long long k0 =
            ((unsigned long long)ord_f32(s0) << 7) | (unsigned)(127 - lane);
        unsigned long long k1 =
            ((unsigned long long)ord_f32(s1) << 7) | (unsigned)(127 - (lane + 32));

        #pragma unroll
        for (int t = 0; t < TOPK; ++t) {
            unsigned long long m = (k0 > k1) ? k0 : k1;
            #pragma unroll
            for (int o = 16; o > 0; o >>= 1) {
                unsigned long long other = __shfl_xor_sync(0xFFFFFFFFu, m, o);
                if (other > m) m = other;
            }
            const int bk = 127 - (int)(m & 127u);
            if (lane == 0) {
                out[OFF_SCORES  + b * TOPK + t] = scb[bk];
                out[OFF_RATINGS + b * TOPK + t] = (float)ratings[b * Kk + bk];
                out[OFF_IDX     + b * TOPK + t] = (float)bk;
                g_topk_idx[b * TOPK + t] = bk;
            }
            if (bk == lane)      k0 = 0ull;
            if (bk == lane + 32) k1 = 0ull;
        }
    }
    __syncthreads();
    if (tid == 0) g_scnt[b] = 0;   // reset for next (graph-replayed) call
}

// ---------------------------------------------------------------------------
// Kernel G: gather (unchanged from R12). Blocks [0,128): small segments
// first; blocks [128, 1312): one full wave grid-striding 2560 h_r 32KB
// chunks, 8 independent f4 ld/st per thread with streaming hints.
// ---------------------------------------------------------------------------
__global__ __launch_bounds__(256) void gather_kernel(
    const float4* __restrict__ s_r,
    const float4* __restrict__ h_r,
    const float4* __restrict__ r_a,
    const float4* __restrict__ r_o,
    const float4* __restrict__ mask,
    const int4*   __restrict__ rb,
    const float4* __restrict__ rm,
    const int4*   __restrict__ re,
    float4* __restrict__ out4)
{
    __shared__ int idx_s[Bq * TOPK];
    if (threadIdx.x < Bq * TOPK) idx_s[threadIdx.x] = g_topk_idx[threadIdx.x];
    __syncthreads();

    if (blockIdx.x >= SM_BLOCKS) {
        for (unsigned u = blockIdx.x - SM_BLOCKS; u < HR_UNITS; u += HR_BLOCKS) {
            const unsigned row   = u >> 5;           // 0..79
            const unsigned chunk = u & 31u;          // 2048 f4 each
            const unsigned b     = row / TOPK;
            const unsigned k     = (unsigned)idx_s[row];
            const float4* src = h_r + (b * Kk + k) * 65536u + chunk * 2048u + threadIdx.x;
            float4*       dst = out4 + V4_HR + row * 65536u + chunk * 2048u + threadIdx.x;
            float4 v[8];
            #pragma unroll
            for (int i = 0; i < 8; ++i) v[i] = __ldcs(src + 256 * i);
            #pragma unroll
            for (int i = 0; i < 8; ++i) __stcs(dst + 256 * i, v[i]);
        }
        return;
    }

    const unsigned stride = SM_BLOCKS * 256u;
    for (unsigned g = blockIdx.x * 256u + threadIdx.x; g < SM_TOTAL; g += stride) {
        if (g < SM_SR_END) {
            const unsigned row = g >> 9;
            const unsigned iv  = g & 511u;
            const unsigned b   = row / TOPK;
            const unsigned k   = (unsigned)idx_s[row];
            out4[V4_SR + g] = s_r[(b * Kk + k) * 512u + iv];
        } else if (g < SM_RA_END) {
            const unsigned local = g - SM_SR_END;
            const unsigned row = local >> 7;
            const unsigned iv  = local & 127u;
            const unsigned b   = row / TOPK;
            const unsigned k   = (unsigned)idx_s[row];
            out4[V4_RA + local] = r_a[(b * Kk + k) * 128u + iv];
        } else if (g < SM_RO_END) {
            const unsigned local = g - SM_RA_END;
            const unsigned row = local >> 7;
            const unsigned iv  = local & 127u;
            const unsigned b   = row / TOPK;
            const unsigned k   = (unsigned)idx_s[row];
            out4[V4_RO + local] = r_o[(b * Kk + k) * 128u + iv];
        } else if (g < SM_MK_END) {
            const unsigned local = g - SM_RO_END;   // == row
            const unsigned b = local / TOPK;
            const unsigned k = (unsigned)idx_s[local];
            out4[V4_MASK + local] = mask[b * Kk + k];
        } else if (g < SM_RB_END) {
            const unsigned local = g - SM_MK_END;
            const unsigned row = local >> 5;
            const unsigned iv  = local & 31u;
            const unsigned b   = row / TOPK;
            const unsigned k   = (unsigned)idx_s[row];
            const int4 v = rb[(b * Kk + k) * 32u + iv];
            out4[V4_RB + local] = make_float4((float)v.x, (float)v.y, (float)v.z, (float)v.w);
        } else if (g < SM_RM_END) {
            const unsigned local = g - SM_RB_END;
            const unsigned row = local >> 5;
            const unsigned iv  = local & 31u;
            const unsigned b   = row / TOPK;
            const unsigned k   = (unsigned)idx_s[row];
            out4[V4_RM + local] = rm[(b * Kk + k) * 32u + iv];
        } else {
            const unsigned local = g - SM_RM_END;
            const unsigned row = local >> 5;
            const unsigned iv  = local & 31u;
            const unsigned b   = row / TOPK;
            const unsigned k   = (unsigned)idx_s[row];
            const int4 v = re[(b * Kk + k) * 32u + iv];
            out4[V4_RE + local] = make_float4((float)v.x, (float)v.y, (float)v.z, (float)v.w);
        }
    }
}

// ---------------------------------------------------------------------------
extern "C" void kernel_launch(void* const* d_in, const int* in_sizes, int n_in,
                              void* d_out, int out_size)
{
    const float* a_s_q   = (const float*)d_in[0];
    const float* a_s_r   = (const float*)d_in[1];
    const float* W       = (const float*)d_in[2];
    const float* s_r     = (const float*)d_in[3];
    const float* h_r     = (const float*)d_in[4];
    const float* r_a     = (const float*)d_in[5];
    const float* r_o     = (const float*)d_in[6];
    const float* mask    = (const float*)d_in[7];
    const int*   rb      = (const int*)d_in[8];
    const float* rm      = (const float*)d_in[9];
    const int*   ratings = (const int*)d_in[10];
    const int*   re      = (const int*)d_in[11];
    float* out = (float*)d_out;

    // opt-in to >48KB dynamic smem (host-side attribute; idempotent)
    static int attr_done = 0;
    if (!attr_done) {
        cudaFuncSetAttribute(q_kernel,
            cudaFuncAttributeMaxDynamicSharedMemorySize, Q_SMEM);
        cudaFuncSetAttribute(score_topk_kernel,
            cudaFuncAttributeMaxDynamicSharedMemorySize, S_SMEM);
        attr_done = 1;
    }

    q_kernel<<<80, 128, Q_SMEM>>>(a_s_q, W);
    score_topk_kernel<<<16, 256, S_SMEM>>>(a_s_r, ratings, out);
    gather_kernel<<<SM_BLOCKS + HR_BLOCKS, 256>>>(
        (const float4*)s_r, (const float4*)h_r, (const float4*)r_a,
        (const float4*)r_o, (const float4*)mask, (const int4*)rb,
        (const float4*)rm, (const int4*)re, (float4*)out);
}

// round 14
// speedup vs baseline: 1.0102x; 1.0087x over previous
#include <cuda_runtime.h>
#include <cuda_bf16.h>
#include <cstdint>

// ---------------------------------------------------------------------------
// Model_70222715289880: bilinear score -> top-k(10/64) -> gather of 10 tensors
// B=8, K=64, TOPK=10, N_R=4, L_R=128, H=512, D=128, D2=640.
//
// R14: R13's kernels (measured-best front) chained with Programmatic
// Dependent Launch. score/gather launch early (PSS attribute); score issues
// its a_s_r prefetch BEFORE cudaGridDependencySynchronize() so its load
// overlaps q's execution; gather griddepsyncs before reading g_topk_idx.
// FP summation order BIT-IDENTICAL to all passing rounds (R2-R13).
// ---------------------------------------------------------------------------

#define Bq   8
#define Kk   64
#define TOPK 10
#define D2   640

#define OFF_SCORES   0
#define OFF_RATINGS  21238160
#define OFF_IDX      21248480

// vec4 (float4) offsets of gathered segments in dst
#define V4_SR    20u
#define V4_HR    40980u
#define V4_RA    5283860u
#define V4_RO    5294100u
#define V4_MASK  5304340u
#define V4_RB    5304420u
#define V4_RM    5306980u
#define V4_RE    5309560u

// small-gather compacted ranges (f4 units), h_r excluded
#define SM_SR_END  40960u
#define SM_RA_END  51200u
#define SM_RO_END  61440u
#define SM_MK_END  61520u
#define SM_RB_END  64080u
#define SM_RM_END  66640u
#define SM_TOTAL   69200u

#define SM_BLOCKS  128
#define HR_UNITS   2560u   // 80 rows * 32 chunks (2048 f4 each)
#define HR_BLOCKS  1184    // one full wave at 8 blocks/SM on 148 SMs

__device__ int      g_topk_idx[Bq * TOPK];
__device__ float    g_q[Bq * D2];
__device__ float    g_sc[Bq * Kk];
__device__ unsigned g_scnt[Bq];   // zero-init; finisher resets each call

// -------------------------------- cp.async --------------------------------
__device__ __forceinline__ void cpa16(uint32_t dst_smem, const void* src) {
    asm volatile("cp.async.cg.shared.global [%0], [%1], 16;"
                 :: "r"(dst_smem), "l"(src));
}
#define CPA_COMMIT()  asm volatile("cp.async.commit_group;")
#define CPA_WAIT(N)   asm volatile("cp.async.wait_group %0;" :: "n"(N) : "memory")

__device__ __forceinline__ uint32_t smem_u32(const void* p) {
    return (uint32_t)__cvta_generic_to_shared(p);
}

// ---------------------------------------------------------------------------
// XLA's tanh (Eigen generic_fast_tanh_float as emitted by elemental_ir_emitter)
// ---------------------------------------------------------------------------
__device__ __forceinline__ float xla_tanhf(float x)
{
    const float kClamp = 7.90531110763549805f;
    float xc = fmaxf(-kClamp, fminf(x, kClamp));
    float x2 = xc * xc;

    float p = fmaf(x2, -2.76076847742355e-16f, 2.00018790482477e-13f);
    p = fmaf(x2, p, -8.60467152213735e-11f);
    p = fmaf(x2, p,  5.12229709037114e-08f);
    p = fmaf(x2, p,  1.48572235717979e-05f);
    p = fmaf(x2, p,  6.37261928875436e-04f);
    p = fmaf(x2, p,  4.89352455891786e-03f);
    p = xc * p;

    float q = fmaf(x2, 1.19825839466702e-06f, 1.18534705686654e-04f);
    q = fmaf(x2, q, 2.26843463243900e-03f);
    q = fmaf(x2, q, 4.89352518554385e-03f);

    float r = p / q;
    return (fabsf(x) < 0.0004f) ? x : r;
}

// total-order key on float (ascending)
__device__ __forceinline__ unsigned ord_f32(float f)
{
    int i = __float_as_int(f);
    return (i < 0) ? ~(unsigned)i : ((unsigned)i | 0x80000000u);
}

// ---------------------------------------------------------------------------
// Kernel Q (R13, 7.58us): 80 blocks x 128. Block (es=bid%20, bg=bid/20):
// e-slice [32es,+32), batches {2bg, 2bg+1}. All 4 warps load; warps 0,1 run
// chains (b = 2bg + w, lane l -> e). Dynamic smem: 87,040 B.
// ---------------------------------------------------------------------------
#define Q_SMEM  ((2 * D2 + D2 * 32) * 4)

__global__ __launch_bounds__(128) void q_kernel(
    const float* __restrict__ a_s_q,
    const float* __restrict__ W)
{
    extern __shared__ float dynq[];
    float* aq = dynq;                 // [2][640]
    float* wt = dynq + 2 * D2;        // [640][32] row stride 32 floats

    const int tid = threadIdx.x;
    const int w   = tid >> 5;
    const int l   = tid & 31;
    const int es  = blockIdx.x % 20;
    const int bg  = blockIdx.x / 20;
    const int e0  = es * 32;

    const uint32_t aq_s = smem_u32(aq);
    const uint32_t wt_s = smem_u32(wt);

    const float* aqsrc = a_s_q + bg * 2 * D2;
    #pragma unroll
    for (int r = 0; r < 3; ++r) {
        const int j = tid + 128 * r;
        if (j < 320) cpa16(aq_s + (uint32_t)j * 16u, aqsrc + j * 4);
    }
    #pragma unroll
    for (int r = 0; r < 40; ++r) {
        const int j   = tid + 128 * r;
        const int row = j >> 3;
        const int c   = j & 7;
        cpa16(wt_s + (uint32_t)j * 16u, W + row * D2 + e0 + c * 4);
    }
    CPA_COMMIT();
    CPA_WAIT(0);
    __syncthreads();

    if (w < 2) {
        const int b = bg * 2 + w;
        const float* aqb = aq + w * D2;
        const float* wl  = wt + l;
        float s = 0.f;
        #pragma unroll 16
        for (int d = 0; d < D2; ++d)
            s = fmaf(aqb[d], wl[d * 32], s);
        g_q[b * D2 + e0 + l] = s;
    }
}

// ---------------------------------------------------------------------------
// Kernel S (R13 + PDL): 16 blocks x 256. Block (b=bid>>1, kh=bid&1) scores
// k in [32kh,+32). PDL: a_s_r prefetch issued BEFORE griddepsync (overlaps
// q); q row loaded after. Chain FP order identical to R2-R13. Second
// finisher per b runs the warp top-k. Dynamic smem: 86,016 B.
// ---------------------------------------------------------------------------
#define SROW2   652
#define S_SMEM  ((D2 + 32 * SROW2) * 4)

__global__ __launch_bounds__(256) void score_topk_kernel(
    const float* __restrict__ a_s_r,
    const int*   __restrict__ ratings,
    float* __restrict__ out)
{
    __shared__ int am_last;
    extern __shared__ float dyns[];
    float* q_s = dyns;             // [640]
    float* at  = dyns + D2;        // [32][652]

    const int b   = blockIdx.x >> 1;
    const int kh  = blockIdx.x & 1;
    const int tid = threadIdx.x;

    // a_s_r rows [32kh, +32): 5120 f4 -> 20 per thread (independent of q!)
    const float* abase = a_s_r + ((size_t)b * Kk + kh * 32) * D2;
    const uint32_t at_s = smem_u32(at);
    #pragma unroll
    for (int r = 0; r < 20; ++r) {
        const int j   = tid + 256 * r;
        const int row = j / 160;
        const int col = j % 160;
        cpa16(at_s + (uint32_t)(row * SROW2 * 4 + col * 16),
              abase + row * D2 + col * 4);
    }
    CPA_COMMIT();

    // wait for q_kernel completion (PDL), then fetch the q row
    cudaGridDependencySynchronize();
    const uint32_t q_ss = smem_u32(q_s);
    if (tid < 160) cpa16(q_ss + (uint32_t)tid * 16u, g_q + b * D2 + tid * 4);
    CPA_COMMIT();
    CPA_WAIT(0);
    __syncthreads();

    if (tid < 128) {
        const int kloc = tid >> 2;       // 0..31
        const int sub  = tid & 3;
        const float* arow = at + kloc * SROW2 + sub;
        const float* qrow = q_s + sub;
        float s = 0.f;
        #pragma unroll 16
        for (int i = 0; i < 160; ++i)
            s = fmaf(qrow[4 * i], arow[4 * i], s);
        s += __shfl_xor_sync(0xFFFFFFFFu, s, 1);
        s += __shfl_xor_sync(0xFFFFFFFFu, s, 2);
        if (sub == 0) g_sc[b * Kk + kh * 32 + kloc] = xla_tanhf(s);
    }
    __syncthreads();

    if (tid == 0) {
        __threadfence();
        unsigned r = atomicAdd(&g_scnt[b], 1u);
        am_last = (r == 1u) ? 1 : 0;
    }
    __syncthreads();
    if (!am_last) return;
    __threadfence();   // order g_sc reads after observing the other half

    if (tid < 32) {
        const int lane = tid;
        const float* scb = g_sc + b * Kk;
        const float s0 = scb[lane];
        const float s1 = scb[lane + 32];
        // key = ord(score) << 7 | (127 - k): max key == max score, min index
        unsigned long long k0 =
            ((unsigned long long)ord_f32(s0) << 7) | (unsigned)(127 - lane);
        unsigned long long k1 =
            ((unsigned long long)ord_f32(s1) << 7) | (unsigned)(127 - (lane + 32));

        #pragma unroll
        for (int t = 0; t < TOPK; ++t) {
            unsigned long long m = (k0 > k1) ? k0 : k1;
            #pragma unroll
            for (int o = 16; o > 0; o >>= 1) {
                unsigned long long other = __shfl_xor_sync(0xFFFFFFFFu, m, o);
                if (other > m) m = other;
            }
            const int bk = 127 - (int)(m & 127u);
            if (lane == 0) {
                out[OFF_SCORES  + b * TOPK + t] = scb[bk];
                out[OFF_RATINGS + b * TOPK + t] = (float)ratings[b * Kk + bk];
                out[OFF_IDX     + b * TOPK + t] = (float)bk;
                g_topk_idx[b * TOPK + t] = bk;
            }
            if (bk == lane)      k0 = 0ull;
            if (bk == lane + 32) k1 = 0ull;
        }
    }
    __syncthreads();
    if (tid == 0) g_scnt[b] = 0;   // reset for next (graph-replayed) call
}

// ---------------------------------------------------------------------------
// Kernel G (R12/R13 + PDL): griddepsync before reading g_topk_idx.
// Blocks [0,128): small segments first; [128,1312): one full wave striding
// 2560 h_r 32KB chunks, 8 independent f4 ld/st per thread, streaming hints.
// ---------------------------------------------------------------------------
__global__ __launch_bounds__(256) void gather_kernel(
    const float4* __restrict__ s_r,
    const float4* __restrict__ h_r,
    const float4* __restrict__ r_a,
    const float4* __restrict__ r_o,
    const float4* __restrict__ mask,
    const int4*   __restrict__ rb,
    const float4* __restrict__ rm,
    const int4*   __restrict__ re,
    float4* __restrict__ out4)
{
    __shared__ int idx_s[Bq * TOPK];
    cudaGridDependencySynchronize();   // wait for score_topk completion (PDL)
    if (threadIdx.x < Bq * TOPK) idx_s[threadIdx.x] = g_topk_idx[threadIdx.x];
    __syncthreads();

    if (blockIdx.x >= SM_BLOCKS) {
        for (unsigned u = blockIdx.x - SM_BLOCKS; u < HR_UNITS; u += HR_BLOCKS) {
            const unsigned row   = u >> 5;           // 0..79
            const unsigned chunk = u & 31u;          // 2048 f4 each
            const unsigned b     = row / TOPK;
            const unsigned k     = (unsigned)idx_s[row];
            const float4* src = h_r + (b * Kk + k) * 65536u + chunk * 2048u + threadIdx.x;
            float4*       dst = out4 + V4_HR + row * 65536u + chunk * 2048u + threadIdx.x;
            float4 v[8];
            #pragma unroll
            for (int i = 0; i < 8; ++i) v[i] = __ldcs(src + 256 * i);
            #pragma unroll
            for (int i = 0; i < 8; ++i) __stcs(dst + 256 * i, v[i]);
        }
        return;
    }

    const unsigned stride = SM_BLOCKS * 256u;
    for (unsigned g = blockIdx.x * 256u + threadIdx.x; g < SM_TOTAL; g += stride) {
        if (g < SM_SR_END) {
            const unsigned row = g >> 9;
            const unsigned iv  = g & 511u;
            const unsigned b   = row / TOPK;
            const unsigned k   = (unsigned)idx_s[row];
            out4[V4_SR + g] = s_r[(b * Kk + k) * 512u + iv];
        } else if (g < SM_RA_END) {
            const unsigned local = g - SM_SR_END;
            const unsigned row = local >> 7;
            const unsigned iv  = local & 127u;
            const unsigned b   = row / TOPK;
            const unsigned k   = (unsigned)idx_s[row];
            out4[V4_RA + local] = r_a[(b * Kk + k) * 128u + iv];
        } else if (g < SM_RO_END) {
            const unsigned local = g - SM_RA_END;
            const unsigned row = local >> 7;
            const unsigned iv  = local & 127u;
            const unsigned b   = row / TOPK;
            const unsigned k   = (unsigned)idx_s[row];
            out4[V4_RO + local] = r_o[(b * Kk + k) * 128u + iv];
        } else if (g < SM_MK_END) {
            const unsigned local = g - SM_RO_END;   // == row
            const unsigned b = local / TOPK;
            const unsigned k = (unsigned)idx_s[local];
            out4[V4_MASK + local] = mask[b * Kk + k];
        } else if (g < SM_RB_END) {
            const unsigned local = g - SM_MK_END;
            const unsigned row = local >> 5;
            const unsigned iv  = local & 31u;
            const unsigned b   = row / TOPK;
            const unsigned k   = (unsigned)idx_s[row];
            const int4 v = rb[(b * Kk + k) * 32u + iv];
            out4[V4_RB + local] = make_float4((float)v.x, (float)v.y, (float)v.z, (float)v.w);
        } else if (g < SM_RM_END) {
            const unsigned local = g - SM_RB_END;
            const unsigned row = local >> 5;
            const unsigned iv  = local & 31u;
            const unsigned b   = row / TOPK;
            const unsigned k   = (unsigned)idx_s[row];
            out4[V4_RM + local] = rm[(b * Kk + k) * 32u + iv];
        } else {
            const unsigned local = g - SM_RM_END;
            const unsigned row = local >> 5;
            const unsigned iv  = local & 31u;
            const unsigned b   = row / TOPK;
            const unsigned k   = (unsigned)idx_s[row];
            const int4 v = re[(b * Kk + k) * 32u + iv];
            out4[V4_RE + local] = make_float4((float)v.x, (float)v.y, (float)v.z, (float)v.w);
        }
    }
}

// ---------------------------------------------------------------------------
extern "C" void kernel_launch(void* const* d_in, const int* in_sizes, int n_in,
                              void* d_out, int out_size)
{
    const float* a_s_q   = (const float*)d_in[0];
    const float* a_s_r   = (const float*)d_in[1];
    const float* W       = (const float*)d_in[2];
    const float* s_r     = (const float*)d_in[3];
    const float* h_r     = (const float*)d_in[4];
    const float* r_a     = (const float*)d_in[5];
    const float* r_o     = (const float*)d_in[6];
    const float* mask    = (const float*)d_in[7];
    const int*   rb      = (const int*)d_in[8];
    const float* rm      = (const float*)d_in[9];
    const int*   ratings = (const int*)d_in[10];
    const int*   re      = (const int*)d_in[11];
    float* out = (float*)d_out;

    static int attr_done = 0;
    if (!attr_done) {
        cudaFuncSetAttribute(q_kernel,
            cudaFuncAttributeMaxDynamicSharedMemorySize, Q_SMEM);
        cudaFuncSetAttribute(score_topk_kernel,
            cudaFuncAttributeMaxDynamicSharedMemorySize, S_SMEM);
        attr_done = 1;
    }

    // kernel 1: plain launch
    q_kernel<<<80, 128, Q_SMEM>>>(a_s_q, W);

    // kernel 2: PDL (launches during q; griddepsyncs before reading g_q)
    {
        cudaLaunchConfig_t cfg = {};
        cfg.gridDim  = dim3(16, 1, 1);
        cfg.blockDim = dim3(256, 1, 1);
        cfg.dynamicSmemBytes = S_SMEM;
        cfg.stream = 0;
        cudaLaunchAttribute at[1];
        at[0].id = cudaLaunchAttributeProgrammaticStreamSerialization;
        at[0].val.programmaticStreamSerializationAllowed = 1;
        cfg.attrs = at;
        cfg.numAttrs = 1;
        cudaLaunchKernelEx(&cfg, score_topk_kernel, a_s_r, ratings, out);
    }

    // kernel 3: PDL (launches during score; griddepsyncs before reading idx)
    {
        cudaLaunchConfig_t cfg = {};
        cfg.gridDim  = dim3(SM_BLOCKS + HR_BLOCKS, 1, 1);
        cfg.blockDim = dim3(256, 1, 1);
        cfg.dynamicSmemBytes = 0;
        cfg.stream = 0;
        cudaLaunchAttribute at[1];
        at[0].id = cudaLaunchAttributeProgrammaticStreamSerialization;
        at[0].val.programmaticStreamSerializationAllowed = 1;
        cfg.attrs = at;
        cfg.numAttrs = 1;
        cudaLaunchKernelEx(&cfg, gather_kernel,
            (const float4*)s_r, (const float4*)h_r, (const float4*)r_a,
            (const float4*)r_o, (const float4*)mask, (const int4*)rb,
            (const float4*)rm, (const int4*)re, (float4*)out);
    }
}